// round 17
// baseline (speedup 1.0000x reference)
#include <cuda_runtime.h>
#include <cuda_fp16.h>
#include <cstdint>

#define B_  2
#define S_  2048
#define D_  1024
#define H_  16
#define DH_ 64

// ---------------------------------------------------------------------------
// Scratch (device globals — no allocation allowed)
// ---------------------------------------------------------------------------
__device__ __half g_xh[3][(size_t)4096 * 1024];  // fp16 of X (q,k,v); [0] reused for ctx
__device__ __half g_wh[4][(size_t)1024 * 1024];  // fp16 of W^T (q,k,v,o)
__device__ __half g_qbh[(size_t)B_ * H_ * S_ * DH_];  // Q fp16 [B,H,S,DH]
__device__ __half g_kbh[(size_t)B_ * H_ * S_ * DH_];  // K fp16
__device__ __half g_vbh[(size_t)B_ * H_ * S_ * DH_];  // V fp16

// ---------------------------------------------------------------------------
__device__ __forceinline__ uint32_t smem_u32(const void* p) {
    uint32_t a;
    asm("{ .reg .u64 t; cvta.to.shared.u64 t, %1; cvt.u32.u64 %0, t; }" : "=r"(a) : "l"(p));
    return a;
}

#define LDMX4(r, addr) \
    asm volatile("ldmatrix.sync.aligned.m8n8.x4.shared.b16 {%0,%1,%2,%3}, [%4];" \
        : "=r"((r)[0]), "=r"((r)[1]), "=r"((r)[2]), "=r"((r)[3]) : "r"(addr))

#define LDMX4T(r, addr) \
    asm volatile("ldmatrix.sync.aligned.m8n8.x4.trans.shared.b16 {%0,%1,%2,%3}, [%4];" \
        : "=r"((r)[0]), "=r"((r)[1]), "=r"((r)[2]), "=r"((r)[3]) : "r"(addr))

#define MMA_F16(d, a, b0, b1) \
    asm volatile("mma.sync.aligned.m16n8k16.row.col.f32.f16.f16.f32 " \
        "{%0,%1,%2,%3}, {%4,%5,%6,%7}, {%8,%9}, {%0,%1,%2,%3};" \
        : "+f"((d)[0]), "+f"((d)[1]), "+f"((d)[2]), "+f"((d)[3]) \
        : "r"((a)[0]), "r"((a)[1]), "r"((a)[2]), "r"((a)[3]), "r"(b0), "r"(b1))

#define CP_ASYNC16(sa, gp) \
    asm volatile("cp.async.cg.shared.global [%0], [%1], 16;" :: "r"(sa), "l"(gp))
#define CP_COMMIT() asm volatile("cp.async.commit_group;" ::: "memory")
#define CP_WAITN(n) asm volatile("cp.async.wait_group %0;" :: "n"(n) : "memory")

__device__ __forceinline__ uint32_t pack_h(float v0, float v1) {
    __half2 h2 = __floats2half2_rn(v0, v1);
    return *reinterpret_cast<uint32_t*>(&h2);
}

// ---------------------------------------------------------------------------
// Fused prep: blocks [0,12288) = fp16 casts of q,k,v;
//             blocks [12288,16384) = transpose + fp16 cast of the 4 weights.
// ---------------------------------------------------------------------------
struct PrepArgs {
    const float *q, *k, *v, *W0, *W1, *W2, *W3;
    __half *xh0, *xh1, *xh2;
};

__global__ __launch_bounds__(256) void prep_kernel(PrepArgs a)
{
    __shared__ float ts[32][33];
    const int bid = blockIdx.x;
    if (bid < 12288) {
        const int z = bid >> 12;
        const int blk = bid & 4095;
        const float* x = (z == 0) ? a.q : (z == 1) ? a.k : a.v;
        __half* hi = (z == 0) ? a.xh0 : (z == 1) ? a.xh1 : a.xh2;
        int i = blk * 256 + threadIdx.x;
        float4 v4 = ((const float4*)x)[i];
        ((uint32_t*)hi)[i * 2]     = pack_h(v4.x, v4.y);
        ((uint32_t*)hi)[i * 2 + 1] = pack_h(v4.z, v4.w);
    } else {
        const int j = bid - 12288;
        const int z = j >> 10;
        const int r = j & 1023;
        const int kb = (r >> 5) << 5, nb = (r & 31) << 5;
        const float* W = (z == 0) ? a.W0 : (z == 1) ? a.W1 : (z == 2) ? a.W2 : a.W3;
        __half* th = g_wh[z];
        int tx = threadIdx.x & 31, ty = threadIdx.x >> 5;
        #pragma unroll
        for (int jj = 0; jj < 4; jj++)
            ts[ty + jj * 8][tx] = W[(size_t)(kb + ty + jj * 8) * 1024 + nb + tx];
        __syncthreads();
        #pragma unroll
        for (int jj = 0; jj < 4; jj++) {
            int n = nb + ty + jj * 8, kk = kb + tx;
            th[(size_t)n * 1024 + kk] = __float2half_rn(ts[tx][ty + jj * 8]);
        }
    }
}

// ---------------------------------------------------------------------------
// fp16 mma.sync GEMM (R16 config): CTA 128x128, K-tile 64, 2-stage, 8 warps
// (64x32), single sync per k-tile. Unchanged.
// ---------------------------------------------------------------------------
struct GB {
    const __half *Ah, *Bh;
    const float* bias;
    float* out; long sB, sS, sH;
    __half *oh;
};
struct GB3 { GB g[3]; };

#define SA_STRIDE 144
#define MAT_BYTES (128 * SA_STRIDE)
#define STG_BYTES (2 * MAT_BYTES)
#define GEMM_SMEM (2 * STG_BYTES)

__global__ __launch_bounds__(256) void gemm_mma_kernel(GB3 P)
{
    const GB p = P.g[blockIdx.z];
    extern __shared__ char sm[];
    const uint32_t sbase = smem_u32(sm);
    const int tid = threadIdx.x, lane = tid & 31, wid = tid >> 5;
    const int wm = wid & 1, wn = wid >> 1;
    const int m0 = blockIdx.y * 128, n0 = blockIdx.x * 128;

    float acc[4][4][4] = {};

    const int arow  = lane & 15;
    const int akoff = (lane >> 4) * 16;
    const int brow  = ((lane >> 4) << 3) | (lane & 7);
    const int bkoff = ((lane >> 3) & 1) * 16;

    #define ISSUE(t) do { \
        const int k0i = (t) * 64; \
        const uint32_t sdst = sbase + ((t) & 1) * STG_BYTES; \
        _Pragma("unroll") \
        for (int i = 0; i < 8; i++) { \
            int idx = tid + i * 256; \
            int mat = idx >> 10, rem = idx & 1023; \
            int row = rem >> 3, c = rem & 7; \
            const __half* gp = (mat ? p.Bh + (size_t)(n0 + row) * 1024 \
                                    : p.Ah + (size_t)(m0 + row) * 1024) + k0i + c * 8; \
            uint32_t sa = sdst + mat * MAT_BYTES + row * SA_STRIDE + c * 16; \
            CP_ASYNC16(sa, gp); \
        } \
        CP_COMMIT(); \
    } while (0)

    ISSUE(0);
    CP_WAITN(0);
    __syncthreads();

    for (int t = 0; t < 16; t++) {
        if (t < 15) ISSUE(t + 1);

        const uint32_t s0  = sbase + (t & 1) * STG_BYTES;
        const uint32_t pAh = s0;
        const uint32_t pBh = s0 + MAT_BYTES;

        #pragma unroll
        for (int ks = 0; ks < 4; ks++) {
            uint32_t ah[4][4];
            #pragma unroll
            for (int mf = 0; mf < 4; mf++) {
                uint32_t ra = (uint32_t)(wm * 64 + mf * 16 + arow) * SA_STRIDE + ks * 32 + akoff;
                LDMX4(ah[mf], pAh + ra);
            }
            uint32_t bh[2][4];
            #pragma unroll
            for (int ng = 0; ng < 2; ng++) {
                uint32_t rb = (uint32_t)(wn * 32 + ng * 16 + brow) * SA_STRIDE + ks * 32 + bkoff;
                LDMX4(bh[ng], pBh + rb);
            }
            #pragma unroll
            for (int mf = 0; mf < 4; mf++)
                #pragma unroll
                for (int nf = 0; nf < 4; nf++) {
                    const uint32_t* bhp = &bh[nf >> 1][(nf & 1) * 2];
                    MMA_F16(acc[mf][nf], ah[mf], bhp[0], bhp[1]);
                }
        }

        if (t < 15) { CP_WAITN(0); __syncthreads(); }
    }

    // ---- epilogue ----
    const int g = lane >> 2, tig = lane & 3;
    const long s2S = DH_, s2H = (long)S_ * DH_, s2B = (long)H_ * S_ * DH_;
    #pragma unroll
    for (int mf = 0; mf < 4; mf++) {
        const int mA = m0 + wm * 64 + mf * 16 + g;
        const int b1 = mA >> 11, s1 = mA & 2047;
        const int b2 = (mA + 8) >> 11, s2 = (mA + 8) & 2047;
        #pragma unroll
        for (int nf = 0; nf < 4; nf++) {
            const int n = n0 + wn * 32 + nf * 8 + tig * 2;
            const int h = n >> 6, d = n & 63;
            const float bv0 = __ldg(p.bias + n), bv1 = __ldg(p.bias + n + 1);
            float p0 = acc[mf][nf][0] + bv0, p1 = acc[mf][nf][1] + bv1;
            float p2 = acc[mf][nf][2] + bv0, p3 = acc[mf][nf][3] + bv1;
            if (p.out) {
                float2 lo_pair, hi_pair;
                lo_pair.x = p0; lo_pair.y = p1;
                hi_pair.x = p2; hi_pair.y = p3;
                *(float2*)(p.out + (size_t)b1 * p.sB + (size_t)s1 * p.sS + (size_t)h * p.sH + d) = lo_pair;
                *(float2*)(p.out + (size_t)b2 * p.sB + (size_t)s2 * p.sS + (size_t)h * p.sH + d) = hi_pair;
            }
            if (p.oh) {
                size_t i1 = (size_t)b1 * s2B + (size_t)s1 * s2S + (size_t)h * s2H + d;
                size_t i2 = (size_t)b2 * s2B + (size_t)s2 * s2S + (size_t)h * s2H + d;
                *(uint32_t*)(p.oh + i1) = pack_h(p0, p1);
                *(uint32_t*)(p.oh + i2) = pack_h(p2, p3);
            }
        }
    }
    #undef ISSUE
}

// ---------------------------------------------------------------------------
// Tensor-core flash attention (fp16, causal, exp2 softmax).
// 128 q/CTA, *8 warps x 16 rows* (256 threads), KV double-buffered,
// single sync per k-tile. ~110 regs -> 2 CTAs/SM = 16 warps/SM.
// ---------------------------------------------------------------------------
#define LOG2E      1.4426950408889634f
#define ASCALE     (0.125f * LOG2E)
#define AMASK      (-10000.0f * LOG2E)

#define QT_BYTES   (128 * 144)
#define KVMAT      (64 * 144)
#define KVSTG      (2 * KVMAT)              // K|V = 18432
#define ATT_SMEM   (QT_BYTES + 2 * KVSTG)   // 55296

__global__ __launch_bounds__(256) void attn_mma_kernel(
    const __half* __restrict__ Qhg,
    const __half* __restrict__ Khg, const __half* __restrict__ Vhg,
    __half* __restrict__ Ohg)
{
    extern __shared__ char sm[];
    const uint32_t sb  = smem_u32(sm);
    const uint32_t sQh = sb;
    const uint32_t sKV = sb + QT_BYTES;

    const int tid = threadIdx.x, lane = tid & 31, wid = tid >> 5;
    const int bidx = blockIdx.x;
    const int qblk = (S_ / 128 - 1) - (bidx >> 5);
    const int hb = bidx & 31;
    const int h = hb & 15, b = hb >> 4;
    const int q0 = qblk * 128;
    const int wrow = wid * 16;                      // 16 rows per warp
    const int g = lane >> 2, tig = lane & 3;

    const size_t hoff = ((size_t)(b * H_ + h) * S_) * DH_;
    const __half* qh_p = Qhg + hoff + (size_t)q0 * DH_;
    const __half* kh_p = Khg + hoff;
    const __half* vh_p = Vhg + hoff;

    #define KV_ISSUE(k0v, st) do { \
        const uint32_t sst = sKV + (st) * KVSTG; \
        _Pragma("unroll") \
        for (int i = 0; i < 4; i++) { \
            int idx = tid + i * 256; \
            int mat = idx >> 9, rem = idx & 511, row = rem >> 3, c = rem & 7; \
            const __half* gp = (mat ? vh_p : kh_p) + (size_t)((k0v) + row) * 64 + c * 8; \
            uint32_t sa = sst + mat * KVMAT + row * 144 + c * 16; \
            CP_ASYNC16(sa, gp); \
        } \
        CP_COMMIT(); \
    } while (0)

    const int ktmax = 2 * qblk + 1;

    // ---- prologue: Q + KV0 in one commit group ----
    #pragma unroll
    for (int i = 0; i < 4; i++) {
        int idx = tid + i * 256;
        int row = idx >> 3, c = idx & 7;
        CP_ASYNC16(sQh + row * 144 + c * 16, qh_p + row * 64 + c * 8);
    }
    KV_ISSUE(0, 0);
    CP_WAITN(0);
    __syncthreads();

    // ---- hoist Q fragments (16 rows -> one x4 per kc) ----
    uint32_t qf[4][4];
    #pragma unroll
    for (int kc = 0; kc < 4; kc++) {
        uint32_t ra = (uint32_t)(wrow + (lane & 15)) * 144
                      + kc * 32 + (lane >> 4) * 16;
        LDMX4(qf[kc], sQh + ra);
    }

    float o[8][4] = {};
    float m_run[2] = {-1e30f, -1e30f};
    float l_run[2] = {};

    for (int kt = 0; kt <= ktmax; kt++) {
        const int k0 = kt * 64;
        const uint32_t sst = sKV + (kt & 1) * KVSTG;
        const uint32_t sKh = sst, sVh = sst + KVMAT;

        if (kt < ktmax) KV_ISSUE(k0 + 64, (kt + 1) & 1);

        // ---- S = Q K^T ----
        float s[8][4] = {};
        #pragma unroll
        for (int kc = 0; kc < 4; kc++) {
            #pragma unroll
            for (int ng = 0; ng < 4; ng++) {
                uint32_t rb = (uint32_t)(ng * 16 + ((lane >> 4) << 3) + (lane & 7)) * 144
                              + kc * 32 + ((lane >> 3) & 1) * 16;
                uint32_t kh[4];
                LDMX4(kh, sKh + rb);
                MMA_F16(s[2*ng],   qf[kc], kh[0], kh[1]);
                MMA_F16(s[2*ng+1], qf[kc], kh[2], kh[3]);
            }
        }

        // ---- scale + causal mask (log2 domain) ----
        const bool maskw = (k0 + 63) > (q0 + wrow);
        #pragma unroll
        for (int nf = 0; nf < 8; nf++)
            #pragma unroll
            for (int r = 0; r < 4; r++) {
                float v = s[nf][r] * ASCALE;
                if (maskw) {
                    int qi = q0 + wrow + g + ((r >= 2) ? 8 : 0);
                    int kj = k0 + nf * 8 + tig * 2 + (r & 1);
                    if (kj > qi) v += AMASK;
                }
                s[nf][r] = v;
            }

        // ---- online softmax (exp2) ----
        float alpha[2];
        #pragma unroll
        for (int h2 = 0; h2 < 2; h2++) {
            float mx = -1e30f;
            #pragma unroll
            for (int nf = 0; nf < 8; nf++)
                mx = fmaxf(mx, fmaxf(s[nf][h2*2], s[nf][h2*2+1]));
            mx = fmaxf(mx, __shfl_xor_sync(0xffffffffu, mx, 1));
            mx = fmaxf(mx, __shfl_xor_sync(0xffffffffu, mx, 2));
            float mn = fmaxf(m_run[h2], mx);
            float sum = 0.f;
            #pragma unroll
            for (int nf = 0; nf < 8; nf++) {
                float p0 = exp2f(s[nf][h2*2]   - mn);
                float p1 = exp2f(s[nf][h2*2+1] - mn);
                s[nf][h2*2]   = p0;
                s[nf][h2*2+1] = p1;
                sum += p0 + p1;
            }
            sum += __shfl_xor_sync(0xffffffffu, sum, 1);
            sum += __shfl_xor_sync(0xffffffffu, sum, 2);
            float a = exp2f(m_run[h2] - mn);
            alpha[h2] = a;
            m_run[h2] = mn;
            l_run[h2] = l_run[h2] * a + sum;
        }

        #pragma unroll
        for (int nf = 0; nf < 8; nf++) {
            o[nf][0] *= alpha[0];
            o[nf][1] *= alpha[0];
            o[nf][2] *= alpha[1];
            o[nf][3] *= alpha[1];
        }

        // ---- O += P V ----
        #pragma unroll
        for (int kc = 0; kc < 4; kc++) {
            uint32_t ph[4];
            ph[0] = pack_h(s[2*kc][0],   s[2*kc][1]);
            ph[1] = pack_h(s[2*kc][2],   s[2*kc][3]);
            ph[2] = pack_h(s[2*kc+1][0], s[2*kc+1][1]);
            ph[3] = pack_h(s[2*kc+1][2], s[2*kc+1][3]);
            #pragma unroll
            for (int ng = 0; ng < 4; ng++) {
                uint32_t rv = (uint32_t)(kc * 16 + ((lane >> 3) & 1) * 8 + (lane & 7)) * 144
                              + ng * 32 + (lane >> 4) * 16;
                uint32_t vh[4];
                LDMX4T(vh, sVh + rv);
                MMA_F16(o[2*ng],   ph, vh[0], vh[1]);
                MMA_F16(o[2*ng+1], ph, vh[2], vh[3]);
            }
        }

        if (kt < ktmax) { CP_WAITN(0); __syncthreads(); }
    }

    // ---- epilogue: ctx -> fp16 into GEMM A buffer ----
    float inv0 = 1.f / l_run[0], inv1 = 1.f / l_run[1];
    const int r0 = q0 + wrow + g;
    const size_t m1 = (size_t)b * 2048 + r0;
    const size_t m2 = m1 + 8;
    #pragma unroll
    for (int nf = 0; nf < 8; nf++) {
        const int col = h * 64 + nf * 8 + tig * 2;
        *(uint32_t*)(Ohg + m1 * 1024 + col) = pack_h(o[nf][0] * inv0, o[nf][1] * inv0);
        *(uint32_t*)(Ohg + m2 * 1024 + col) = pack_h(o[nf][2] * inv1, o[nf][3] * inv1);
    }
    #undef KV_ISSUE
}

// ---------------------------------------------------------------------------
extern "C" void kernel_launch(void* const* d_in, const int* in_sizes, int n_in,
                              void* d_out, int out_size)
{
    const float* q  = (const float*)d_in[0];
    const float* k  = (const float*)d_in[1];
    const float* v  = (const float*)d_in[2];
    const float* Wq = (const float*)d_in[4];
    const float* bq = (const float*)d_in[5];
    const float* Wk = (const float*)d_in[6];
    const float* bk = (const float*)d_in[7];
    const float* Wv = (const float*)d_in[8];
    const float* bv = (const float*)d_in[9];
    const float* Wo = (const float*)d_in[10];
    const float* bo = (const float*)d_in[11];

    float* out = (float*)d_out;                       // [B,S,D]
    float* present = out + (size_t)B_ * S_ * D_;      // [B,2,H,S,DH]

    __half *xh0, *xh1, *xh2;
    __half *wh0, *wh1, *wh2, *wh3;
    __half *qbh, *kbh, *vbh;
    cudaGetSymbolAddress((void**)&xh0, g_xh);
    cudaGetSymbolAddress((void**)&wh0, g_wh);
    cudaGetSymbolAddress((void**)&qbh, g_qbh);
    cudaGetSymbolAddress((void**)&kbh, g_kbh);
    cudaGetSymbolAddress((void**)&vbh, g_vbh);
    const size_t XSZ = (size_t)4096 * 1024, WSZ = (size_t)1024 * 1024;
    xh1 = xh0 + XSZ; xh2 = xh0 + 2 * XSZ;
    wh1 = wh0 + WSZ; wh2 = wh0 + 2 * WSZ; wh3 = wh0 + 3 * WSZ;

    const long sB_head = (long)H_ * S_ * DH_;
    const long sH_head = (long)S_ * DH_;

    cudaFuncSetAttribute(gemm_mma_kernel, cudaFuncAttributeMaxDynamicSharedMemorySize, GEMM_SMEM);
    cudaFuncSetAttribute(attn_mma_kernel, cudaFuncAttributeMaxDynamicSharedMemorySize, ATT_SMEM);

    // fused prep
    PrepArgs pa = {q, k, v, Wq, Wk, Wv, Wo, xh0, xh1, xh2};
    prep_kernel<<<16384, 256>>>(pa);

    // fused Q/K/V projections
    GB3 P;
    P.g[0] = {xh0, wh0, bq, nullptr, 0, 0, 0, qbh};
    P.g[1] = {xh1, wh1, bk, present, 2 * sB_head, (long)DH_, sH_head, kbh};
    P.g[2] = {xh2, wh2, bv, present + (size_t)sB_head,
              2 * sB_head, (long)DH_, sH_head, vbh};
    gemm_mma_kernel<<<dim3(8, 32, 3), 256, GEMM_SMEM>>>(P);

    // attention: ctx written as fp16 into g_xh[0]
    attn_mma_kernel<<<(S_ / 128) * H_ * B_, 256, ATT_SMEM>>>(qbh, kbh, vbh, xh0);

    // output projection: out = ctx @ Wo + bo
    GB3 PO;
    PO.g[0] = {xh0, wh3, bo, out, (long)S_ * D_, (long)D_, (long)DH_, nullptr};
    PO.g[1] = PO.g[0];
    PO.g[2] = PO.g[0];
    gemm_mma_kernel<<<dim3(8, 32, 1), 256, GEMM_SMEM>>>(PO);
}